// round 16
// baseline (speedup 1.0000x reference)
#include <cuda_runtime.h>
#include <math.h>

#define NB 64
#define CC 256
#define TT 64
#define VV 25
#define HID 16
#define NCV (NB*CC)            // 16384 (n,c) chunks
#define CHUNK (TT*VV)          // 1600 floats per (n,c)

#define CPB 2                  // chunks per block
#define THREADS 256

#define G 2                    // pipeline groups
#define NBG (NB/G)             // 32 batches per group
#define GCH (NBG*CC)           // 8192 chunks per group (52.4 MB)
#define GBLK (GCH/CPB)         // 4096 blocks per group-pass
#define BPB 128                // reduce blocks per batch (CC/CPB)

__device__ float g_avg[NCV];
__device__ float g_mx[NCV];
__device__ float g_gates[NB * 5 * CC];
__device__ unsigned g_ctr[NB];     // monotonic: +BPB per batch per replay (epoch-safe)

__constant__ int c_perm[VV] = {0,1,2,3,20,  8,9,10,11,23,24,  16,17,18,19,  4,5,6,7,21,22,  12,13,14,15};
__constant__ int c_grp[VV]  = {0,0,0,0,0,   1,1,1,1,1,1,      2,2,2,2,      3,3,3,3,3,3,    4,4,4,4};

// ---------------- scale body ----------------
__device__ __forceinline__ void scale_block(const float* __restrict__ x, float* __restrict__ out,
                                            int base, int tid, float* sx, float* sgate, int* sperm) {
    const float4* __restrict__ src = reinterpret_cast<const float4*>(x + (size_t)base * CHUNK);
    float4* __restrict__ dst = reinterpret_cast<float4*>(out + (size_t)base * CHUNK);

    if (tid < VV) sperm[tid] = c_perm[tid];
    if (tid >= 32 && tid < 32 + CPB * VV) {
        int q = tid - 32, cl = q / VV, j = q - cl * VV;
        int nc = base + cl;
        sgate[cl * 32 + j] = g_gates[(nc >> 8) * (5 * CC) + c_grp[j] * CC + (nc & (CC - 1))];
    }
#pragma unroll
    for (int idx = tid; idx < CPB * CHUNK / 4; idx += THREADS)
        reinterpret_cast<float4*>(sx)[idx] = src[idx];
    __syncthreads();

#pragma unroll
    for (int idx = tid; idx < CPB * CHUNK / 4; idx += THREADS) {
        int e0 = idx * 4;
        int cl = e0 / CHUNK;
        int rem = e0 - cl * CHUNK;
        float r[4];
#pragma unroll
        for (int k = 0; k < 4; k++) {
            int e = rem + k;
            int t = e / VV;
            int j = e - t * VV;
            r[k] = sx[cl * CHUNK + t * VV + sperm[j]] * sgate[cl * 32 + j];
        }
        __stcs(&dst[idx], make_float4(r[0], r[1], r[2], r[3]));
    }
}

// ---------------- reduce body + NON-BLOCKING gate tail (last arriver per batch) ----------------
struct MlpSmem { float spa[CC], spm[CC], parts[160], hidv[80]; unsigned last; };

__device__ __forceinline__ void reduce_block(const float* __restrict__ x, int base, int tid,
                                             float* sx, float* ps, float* pm, MlpSmem* ms,
                                             const float* __restrict__ W1, const float* __restrict__ b1,
                                             const float* __restrict__ W2, const float* __restrict__ b2) {
    const int n = base >> 8;
    const float4* __restrict__ src = reinterpret_cast<const float4*>(x + (size_t)base * CHUNK);
#pragma unroll
    for (int idx = tid; idx < CPB * CHUNK / 4; idx += THREADS)
        reinterpret_cast<float4*>(sx)[idx] = src[idx];
    __syncthreads();

    const int cl = tid >> 7, r = tid & 127;
    float s = 0.f, m = -INFINITY;
    if (r < TT) {
        const float* row = sx + cl * CHUNK + r * VV;       // stride 25: conflict-free banks
        float v0 = row[0], v1 = row[1], v2 = row[2], v3 = row[3], v4 = row[20];
        s = (v0 + v1) + (v2 + v3) + v4;
        m = fmaxf(fmaxf(v0, v1), fmaxf(fmaxf(v2, v3), v4));
    }
#pragma unroll
    for (int o = 16; o; o >>= 1) {
        s += __shfl_xor_sync(0xffffffffu, s, o);
        m = fmaxf(m, __shfl_xor_sync(0xffffffffu, m, o));
    }
    const int wid = tid >> 5, lane = tid & 31;
    if (lane == 0) { ps[wid] = s; pm[wid] = m; }
    __syncthreads();
    if (tid < CPB) {
        g_avg[base + tid] = (ps[tid * 4] + ps[tid * 4 + 1]) * (1.0f / 320.0f);
        g_mx [base + tid] = fmaxf(pm[tid * 4], pm[tid * 4 + 1]);
    }
    __threadfence();                                  // release: stats before arrival
    __syncthreads();
    if (tid == 0) ms->last = (atomicAdd(&g_ctr[n], 1u) % BPB) == (BPB - 1);
    __syncthreads();
    if (!ms->last) return;

    // -------- last arriver: compute ALL gates of batch n (no one waits on this) --------
    __threadfence();                                  // acquire: peers' stats visible
    ms->spa[tid] = g_avg[n * CC + tid];
    ms->spm[tid] = g_mx [n * CC + tid];
    __syncthreads();
    if (tid < 160) {                                  // (branch, f*16+h) dot over C
        const int which = tid >= 80;
        const int i = tid - which * 80;
        const float* w1row = W1 + i * CC;
        const float* p = which ? ms->spm : ms->spa;
        float acc = 0.f;
#pragma unroll 8
        for (int c = 0; c < CC; c++) acc = fmaf(w1row[c], p[c], acc);
        ms->parts[tid] = acc;
    }
    __syncthreads();
    if (tid < 80) {
        float b = b1[tid];
        ms->hidv[tid] = fmaxf(ms->parts[tid] + b, 0.f) + fmaxf(ms->parts[80 + tid] + b, 0.f);
    }
    __syncthreads();
#pragma unroll
    for (int q = tid; q < 5 * CC; q += THREADS) {     // gate per (f, c)
        const int f = q >> 8, c = q & (CC - 1);
        const float* w2row = W2 + ((size_t)f * CC + c) * HID;
        float o = 2.0f * b2[f * CC + c];
#pragma unroll
        for (int h = 0; h < HID; h++) o = fmaf(ms->hidv[f * HID + h], w2row[h], o);
        g_gates[n * (5 * CC) + q] = 1.0f / (1.0f + expf(-o));
    }
    // gates visible to the NEXT kernel launch via launch-boundary ordering
}

// ---------------- combined pipeline kernel ----------------
__global__ __launch_bounds__(THREADS) void comb_kernel(const float* __restrict__ x,
                                                       float* __restrict__ out,
                                                       const float* __restrict__ W1,
                                                       const float* __restrict__ b1,
                                                       const float* __restrict__ W2,
                                                       const float* __restrict__ b2,
                                                       int rg, int sg) {
    __shared__ float sx[CPB * CHUNK];      // 12.8 KB
    __shared__ float saux[64];             // reduce: ps/pm | scale: sgate
    __shared__ int   sperm[32];
    __shared__ MlpSmem ms;                 // gate-tail scratch (~2.6 KB)
    const int tid = threadIdx.x;

    if (rg == 0 && sg < 0 && blockIdx.x < 8) {       // warm weights for the gate tails
        const int gid = blockIdx.x * THREADS + tid;
        if (gid < 640) {
            asm volatile("prefetch.global.L2 [%0];" :: "l"(W1 + gid * 32));
            asm volatile("prefetch.global.L2 [%0];" :: "l"(W2 + gid * 32));
        }
        if (gid < 40)
            asm volatile("prefetch.global.L2 [%0];" :: "l"(b2 + gid * 32));
    }

    bool doScale; int idx;
    if (rg >= 0 && sg >= 0) { doScale = !(blockIdx.x & 1); idx = blockIdx.x >> 1; }  // interleave
    else if (sg >= 0)       { doScale = true;  idx = blockIdx.x; }
    else                    { doScale = false; idx = blockIdx.x; }

    if (doScale) {
        const int base = sg * GCH + (GBLK - 1 - idx) * CPB;      // LIFO within group
        scale_block(x, out, base, tid, sx, saux, sperm);
    } else {
        const int base = rg * GCH + idx * CPB;
        reduce_block(x, base, tid, sx, saux, saux + 8, &ms, W1, b1, W2, b2);
    }
}

extern "C" void kernel_launch(void* const* d_in, const int* in_sizes, int n_in,
                              void* d_out, int out_size) {
    const float* x  = (const float*)d_in[0];
    const float* W1 = (const float*)d_in[1];
    const float* b1 = (const float*)d_in[2];
    const float* W2 = (const float*)d_in[3];
    const float* b2 = (const float*)d_in[4];
    float* out = (float*)d_out;

    // 3 launches, zero mlp kernels: gates ride as last-arriver tails inside reduce passes.
    comb_kernel<<<GBLK,     THREADS>>>(x, out, W1, b1, W2, b2, 0, -1);  // reduce g0 (+gates g0)
    comb_kernel<<<2 * GBLK, THREADS>>>(x, out, W1, b1, W2, b2, 1, 0);   // reduce g1 (+gates g1) | scale g0
    comb_kernel<<<GBLK,     THREADS>>>(x, out, W1, b1, W2, b2, -1, 1);  // scale g1
}

// round 17
// speedup vs baseline: 5.7471x; 5.7471x over previous
#include <cuda_runtime.h>
#include <math.h>

#define NB 64
#define CC 256
#define TT 64
#define VV 25
#define HID 16
#define NCV (NB*CC)            // 16384 (n,c) chunks
#define CHUNK (TT*VV)          // 1600 floats per (n,c)

#define CPB 2                  // chunks per block (scale + reduce)
#define SCALE_THREADS 256

// scratch (allocation-free rule: __device__ globals)
__device__ float g_avg[NCV];
__device__ float g_mx[NCV];
__device__ float g_gates[NB * 5 * CC];

// output joint -> input joint (TORSO, LEFT_HAND, LEFT_LEG, RIGHT_HAND, RIGHT_LEG)
__constant__ int c_perm[VV] = {0,1,2,3,20,  8,9,10,11,23,24,  16,17,18,19,  4,5,6,7,21,22,  12,13,14,15};
__constant__ int c_grp[VV]  = {0,0,0,0,0,   1,1,1,1,1,1,      2,2,2,2,      3,3,3,3,3,3,    4,4,4,4};

// ---------------- K1: torso mean/max per (n,c), coalesced via SMEM staging (R5 body) ----------------
__global__ __launch_bounds__(256) void reduce_kernel(const float* __restrict__ x) {
    __shared__ float sx[CPB * CHUNK];      // 12.8 KB
    __shared__ float ps[8], pm[8];
    const int tid = threadIdx.x;
    const int base = blockIdx.x * CPB;
    const float4* __restrict__ src = reinterpret_cast<const float4*>(x + (size_t)base * CHUNK);

#pragma unroll
    for (int idx = tid; idx < CPB * CHUNK / 4; idx += 256)
        reinterpret_cast<float4*>(sx)[idx] = src[idx];
    __syncthreads();

    const int cl = tid >> 7;               // chunk-local 0..1
    const int r  = tid & 127;
    float s = 0.f, m = -INFINITY;
    if (r < TT) {
        const float* row = sx + cl * CHUNK + r * VV;   // stride 25: conflict-free banks
        float v0 = row[0], v1 = row[1], v2 = row[2], v3 = row[3], v4 = row[20];
        s = (v0 + v1) + (v2 + v3) + v4;
        m = fmaxf(fmaxf(v0, v1), fmaxf(fmaxf(v2, v3), v4));
    }
#pragma unroll
    for (int o = 16; o; o >>= 1) {
        s += __shfl_xor_sync(0xffffffffu, s, o);
        m = fmaxf(m, __shfl_xor_sync(0xffffffffu, m, o));
    }
    const int wid = tid >> 5, lane = tid & 31;
    if (lane == 0) { ps[wid] = s; pm[wid] = m; }
    __syncthreads();
    if (tid < CPB) {
        g_avg[base + tid] = (ps[tid * 4] + ps[tid * 4 + 1]) * (1.0f / 320.0f);
        g_mx[base + tid]  = fmaxf(pm[tid * 4], pm[tid * 4 + 1]);
    }
}

// ---------------- K2: mlp with PDL — weight prologue BEFORE grid-dependency sync ----------------
__global__ void mlp_kernel(const float* __restrict__ W1, const float* __restrict__ b1,
                           const float* __restrict__ W2, const float* __restrict__ b2) {
    const int blk = blockIdx.x;          // n*5 + f
    const int n = blk / 5, f = blk % 5;
    __shared__ float pa[CC], pm[CC], hs[HID];
    const int tid = threadIdx.x, w = tid >> 5, lane = tid & 31;

    // ---- prologue (independent of reduce): preload all weights into registers ----
    float w1v[2][8], b1v[2];
#pragma unroll
    for (int hh = 0; hh < 2; hh++) {
        const int h = w * 2 + hh;
        const float* r = W1 + (f * HID + h) * CC;
#pragma unroll
        for (int k = 0; k < 8; k++) w1v[hh][k] = r[lane + 32 * k];
        b1v[hh] = b1[f * HID + h];
    }
    float w2v[HID];
    const float* w2row = W2 + ((size_t)f * CC + tid) * HID;
#pragma unroll
    for (int h = 0; h < HID; h++) w2v[h] = w2row[h];
    const float b2v = b2[f * CC + tid];

    cudaGridDependencySynchronize();     // wait for reduce's stats

    pa[tid] = g_avg[n * CC + tid];
    pm[tid] = g_mx[n * CC + tid];
    __syncthreads();

#pragma unroll
    for (int hh = 0; hh < 2; hh++) {
        float sa = 0.f, sm = 0.f;
#pragma unroll
        for (int k = 0; k < 8; k++) {
            const int c = lane + 32 * k;
            sa = fmaf(w1v[hh][k], pa[c], sa);
            sm = fmaf(w1v[hh][k], pm[c], sm);
        }
#pragma unroll
        for (int o = 16; o; o >>= 1) {
            sa += __shfl_xor_sync(0xffffffffu, sa, o);
            sm += __shfl_xor_sync(0xffffffffu, sm, o);
        }
        if (lane == 0)
            hs[w * 2 + hh] = fmaxf(sa + b1v[hh], 0.f) + fmaxf(sm + b1v[hh], 0.f);
    }
    __syncthreads();

    float o = 2.0f * b2v;
#pragma unroll
    for (int h = 0; h < HID; h++) o = fmaf(hs[h], w2v[h], o);
    g_gates[n * (5 * CC) + f * CC + tid] = 1.0f / (1.0f + expf(-o));
}

// ---------------- K3: scale with PDL — bulk x read BEFORE grid-dependency sync ----------------
__global__ __launch_bounds__(SCALE_THREADS) void scale_kernel(const float* __restrict__ x,
                                                              float* __restrict__ out) {
    __shared__ float sx[CPB * CHUNK];   // 12.8 KB
    __shared__ float sgate[CPB * 32];
    __shared__ int   sperm[32];
    const int tid = threadIdx.x;
    const int base = (gridDim.x - 1 - blockIdx.x) * CPB;   // LIFO vs reduce's stream order
    const float4* __restrict__ src = reinterpret_cast<const float4*>(x + (size_t)base * CHUNK);
    float4* __restrict__ dst = reinterpret_cast<float4*>(out + (size_t)base * CHUNK);

    // ---- prologue (independent of mlp): permutation LUT + the whole x tile ----
    if (tid < VV) sperm[tid] = c_perm[tid];
#pragma unroll
    for (int idx = tid; idx < CPB * CHUNK / 4; idx += SCALE_THREADS)
        reinterpret_cast<float4*>(sx)[idx] = src[idx];

    cudaGridDependencySynchronize();     // wait for mlp's gates

    if (tid < CPB * VV) {
        int cl = tid / VV, j = tid - cl * VV;
        int nc = base + cl;
        sgate[cl * 32 + j] = g_gates[(nc >> 8) * (5 * CC) + c_grp[j] * CC + (nc & (CC - 1))];
    }
    __syncthreads();

#pragma unroll
    for (int idx = tid; idx < CPB * CHUNK / 4; idx += SCALE_THREADS) {
        int e0 = idx * 4;
        int cl = e0 / CHUNK;
        int rem = e0 - cl * CHUNK;
        float r[4];
#pragma unroll
        for (int k = 0; k < 4; k++) {
            int e = rem + k;
            int t = e / VV;
            int j = e - t * VV;
            r[k] = sx[cl * CHUNK + t * VV + sperm[j]] * sgate[cl * 32 + j];
        }
        __stcs(&dst[idx], make_float4(r[0], r[1], r[2], r[3]));
    }
}

extern "C" void kernel_launch(void* const* d_in, const int* in_sizes, int n_in,
                              void* d_out, int out_size) {
    const float* x  = (const float*)d_in[0];
    const float* W1 = (const float*)d_in[1];
    const float* b1 = (const float*)d_in[2];
    const float* W2 = (const float*)d_in[3];
    const float* b2 = (const float*)d_in[4];
    float* out = (float*)d_out;

    reduce_kernel<<<NCV / CPB, 256>>>(x);                // primary

    cudaLaunchAttribute attr[1];
    attr[0].id = cudaLaunchAttributeProgrammaticStreamSerialization;
    attr[0].val.programmaticStreamSerializationAllowed = 1;

    {   // mlp: PDL-dependent on reduce (weight prologue overlaps reduce tail)
        cudaLaunchConfig_t cfg = {};
        cfg.gridDim = dim3(NB * 5); cfg.blockDim = dim3(256);
        cfg.attrs = attr; cfg.numAttrs = 1;
        cudaLaunchKernelEx(&cfg, mlp_kernel, W1, b1, W2, b2);
    }
    {   // scale: PDL-dependent on mlp (bulk x read overlaps mlp + reduce tail)
        cudaLaunchConfig_t cfg = {};
        cfg.gridDim = dim3(NCV / CPB); cfg.blockDim = dim3(SCALE_THREADS);
        cfg.attrs = attr; cfg.numAttrs = 1;
        cudaLaunchKernelEx(&cfg, scale_kernel, x, out);
    }
}